// round 9
// baseline (speedup 1.0000x reference)
#include <cuda_runtime.h>
#include <cuda_fp16.h>
#include <cstdint>

// ROI Align, P=7, S=2, SCALE=0.125
// x: (8, 256, 100, 100) fp32   rois: (512, 5) fp32   out: (512, 256, 7, 7) fp32
//
// 1) transpose_kernel: NCHW fp32 -> NHWC-128 fp16 slabs (41MB), float2 loads.
//    Channel order inside a pixel is PERMUTED: slab half position p = 4l+k
//    holds logical channel c = 32k + l  (lane l of the main kernel then owns
//    channels {l, l+32, l+64, l+96} -> sout STS at stride 49 = bank-free).
// 2) roi_fp16: block=(roi, cg2). Warp = 128 channels of one bin; each tap is
//    one LDG.64 (256B/warp). fp32 accumulation; conflict-free smem staging.

#define C_    256
#define H_    100
#define W_    100
#define HW_   10000
#define R_    512
#define CPG   128                  // channels per slab
#define NCG   2                    // slabs per image
#define PIXU2 (CPG / 4)            // uint2 per pixel = 32
#define ROWU2 (W_ * PIXU2)         // uint2 per row = 3200

// fp16 slabs as uint array: 8 * 2 * 10000 * 64 uints = 40.96 MB
__device__ unsigned int g_xt[8 * NCG * HW_ * (CPG / 2)];

__device__ __forceinline__ void axis_terms(float c, int L,
                                           int& lo, int& hi,
                                           float& wlo, float& whi) {
    bool valid = (c > -1.0f) && (c < (float)L);
    float cc = fminf(fmaxf(c, 0.0f), (float)(L - 1));
    int l = (int)floorf(cc);
    if (l > L - 1) l = L - 1;
    int h = min(l + 1, L - 1);
    float frac = cc - (float)l;
    lo = l; hi = h;
    wlo = valid ? (1.0f - frac) : 0.0f;
    whi = valid ? frac : 0.0f;
}

// block = (b, cg, y): 128 channels x 100 px -> fp16 channel-major (permuted).
__global__ void __launch_bounds__(256)
transpose_kernel(const float* __restrict__ x) {
    __shared__ unsigned int s2[W_ * 65];   // [xx][u] half2, stride 65 -> bank-free

    const int blk = blockIdx.x;
    const int y   = blk % H_;
    const int t2  = blk / H_;
    const int cg  = t2 & (NCG - 1);
    const int b   = t2 >> 1;
    const int tid = threadIdx.x;

    const float* srcb = x + ((size_t)(b * C_ + cg * CPG)) * HW_ + y * W_;

    // phase 1: u in [0,64) x x2 in [0,50). Slab uint u packs logical channels
    // (cA, cA+32) with cA = 64*(u&1) + u/2  => slab pos p=4l+k <-> c=32k+l.
    // LDG.64 coalesced (lanes along x2); STS lane-stride 130 mod 32 = 2.
    for (int i = tid; i < 64 * 50; i += 256) {
        int u  = i / 50;
        int x2 = i - u * 50;
        int cA = ((u & 1) << 6) + (u >> 1);
        float2 a = __ldg((const float2*)(srcb + cA * HW_) + x2);
        float2 c = __ldg((const float2*)(srcb + (cA + 32) * HW_) + x2);
        __half2 h0 = __floats2half2_rn(a.x, c.x);
        __half2 h1 = __floats2half2_rn(a.y, c.y);
        s2[(2 * x2) * 65 + u]     = *(unsigned int*)&h0;
        s2[(2 * x2 + 1) * 65 + u] = *(unsigned int*)&h1;
    }
    __syncthreads();

    // phase 2: 100 px x 16 uint4; STG.128 coalesced
    unsigned int* dst = g_xt + ((size_t)((b * NCG + cg) * HW_) + (size_t)y * W_) * (CPG / 2);
    for (int j = tid; j < W_ * 16; j += 256) {
        int px = j >> 4;
        int q  = j & 15;
        const unsigned int* sp = s2 + px * 65 + 4 * q;
        uint4 v = make_uint4(sp[0], sp[1], sp[2], sp[3]);
        *(uint4*)(dst + px * 64 + 4 * q) = v;
    }
}

__device__ __forceinline__ float4 hrow(const uint2* __restrict__ p, int dx,
                                       float w0, float w1, float w2, float w3) {
    uint2 t0 = __ldg(p);
    uint2 t1 = __ldg(p + PIXU2);
    uint2 t2 = __ldg(p + dx);
    uint2 t3 = __ldg(p + dx + PIXU2);

    float2 a0 = __half22float2(*(__half2*)&t0.x), a1 = __half22float2(*(__half2*)&t0.y);
    float2 b0 = __half22float2(*(__half2*)&t1.x), b1 = __half22float2(*(__half2*)&t1.y);
    float2 c0 = __half22float2(*(__half2*)&t2.x), c1 = __half22float2(*(__half2*)&t2.y);
    float2 d0 = __half22float2(*(__half2*)&t3.x), d1 = __half22float2(*(__half2*)&t3.y);

    float4 h;
    h.x = fmaf(w0, a0.x, fmaf(w1, b0.x, fmaf(w2, c0.x, w3 * d0.x)));
    h.y = fmaf(w0, a0.y, fmaf(w1, b0.y, fmaf(w2, c0.y, w3 * d0.y)));
    h.z = fmaf(w0, a1.x, fmaf(w1, b1.x, fmaf(w2, c1.x, w3 * d1.x)));
    h.w = fmaf(w0, a1.y, fmaf(w1, b1.y, fmaf(w2, c1.y, w3 * d1.y)));
    return h;
}

// block = (roi, cg2), 256 threads / 8 warps over 49 bins.
__global__ void __launch_bounds__(256)
roi_fp16(const float* __restrict__ rois, float* __restrict__ out) {
    __shared__ int4  sg[28];          // y: {lo*3200, hi*3200, wy0*.25, wy1*.25}
                                      // x: {xb*32, wx0, wx1, -}   (uint2 units)
    __shared__ __align__(16) float sout[CPG * 49];  // 25.1 KB, logical-c-major

    const int r   = blockIdx.x >> 1;
    const int cg  = blockIdx.x & 1;
    const int tid = threadIdx.x;

    const float* roi = rois + (size_t)r * 5;
    float r0 = __ldg(roi + 0);
    float r1 = __ldg(roi + 1);
    float r2 = __ldg(roi + 2);
    float r3 = __ldg(roi + 3);
    float r4 = __ldg(roi + 4);

    const int b = (int)r0;
    const float sx = r1 * 0.125f - 0.5f;
    const float sy = r2 * 0.125f - 0.5f;
    const float bw = (r3 * 0.125f - 0.5f - sx) * (1.0f / 7.0f);
    const float bh = (r4 * 0.125f - 0.5f - sy) * (1.0f / 7.0f);

    if (tid < 14) {
        int s = tid;
        float pos = fmaf((float)(s >> 1) + ((s & 1) ? 0.75f : 0.25f), bh, sy);
        int lo, hi; float w0, w1;
        axis_terms(pos, H_, lo, hi, w0, w1);
        sg[s] = make_int4(lo * ROWU2, hi * ROWU2,
                          __float_as_int(w0 * 0.25f), __float_as_int(w1 * 0.25f));
    } else if (tid >= 16 && tid < 30) {
        int s2 = tid - 16;
        float pos = fmaf((float)(s2 >> 1) + ((s2 & 1) ? 0.75f : 0.25f), bw, sx);
        int lo, hi; float w0, w1;
        axis_terms(pos, W_, lo, hi, w0, w1);
        int xb; float v0, v1;
        if (lo == W_ - 1) { xb = W_ - 2; v0 = 0.0f; v1 = w0 + w1; }
        else              { xb = lo;     v0 = w0;   v1 = w1; }
        sg[14 + s2] = make_int4(xb * PIXU2,
                                __float_as_int(v0), __float_as_int(v1), 0);
    }
    __syncthreads();

    const int warp = tid >> 5;
    const int lane = tid & 31;
    const uint2* base = (const uint2*)g_xt
                      + (size_t)(b * NCG + cg) * (HW_ * PIXU2) + lane;

    for (int bin = warp; bin < 49; bin += 8) {
        int ph = (bin * 147) >> 10;       // bin / 7 for bin < 49
        int pw = bin - ph * 7;

        int4 gy0 = sg[2 * ph];
        int4 gy1 = sg[2 * ph + 1];
        int4 gx0 = sg[14 + 2 * pw];
        int4 gx1 = sg[14 + 2 * pw + 1];

        const uint2* p0 = base + gy0.x + gx0.x;
        const uint2* p1 = base + gy0.y + gx0.x;
        const uint2* p2 = base + gy1.x + gx0.x;
        const uint2* p3 = base + gy1.y + gx0.x;
        const int dx = gx1.x - gx0.x;

        const float wx0 = __int_as_float(gx0.y), wx1 = __int_as_float(gx0.z);
        const float wx2 = __int_as_float(gx1.y), wx3 = __int_as_float(gx1.z);

        float4 h0 = hrow(p0, dx, wx0, wx1, wx2, wx3);
        float4 h1 = hrow(p1, dx, wx0, wx1, wx2, wx3);
        float4 h2 = hrow(p2, dx, wx0, wx1, wx2, wx3);
        float4 h3 = hrow(p3, dx, wx0, wx1, wx2, wx3);

        const float wyA0 = __int_as_float(gy0.z), wyA1 = __int_as_float(gy0.w);
        const float wyB0 = __int_as_float(gy1.z), wyB1 = __int_as_float(gy1.w);

        // lane holds logical channels {lane, lane+32, lane+64, lane+96}
        // -> STS lane-stride 49 words (odd) => conflict-free
        float* so = sout + lane * 49 + bin;
        so[0]       = wyA0 * h0.x + wyA1 * h1.x + wyB0 * h2.x + wyB1 * h3.x;
        so[32 * 49] = wyA0 * h0.y + wyA1 * h1.y + wyB0 * h2.y + wyB1 * h3.y;
        so[64 * 49] = wyA0 * h0.z + wyA1 * h1.z + wyB0 * h2.z + wyB1 * h3.z;
        so[96 * 49] = wyA0 * h0.w + wyA1 * h1.w + wyB0 * h2.w + wyB1 * h3.w;
    }
    __syncthreads();

    // output copy: 1568 float4s, LDS.128 + STG.128 coalesced
    float4* op = (float4*)(out + ((size_t)r * C_ + cg * CPG) * 49);
    const float4* sp = (const float4*)sout;
#pragma unroll
    for (int i = tid; i < CPG * 49 / 4; i += 256)
        op[i] = sp[i];
}

extern "C" void kernel_launch(void* const* d_in, const int* in_sizes, int n_in,
                              void* d_out, int out_size) {
    const float* x    = (const float*)d_in[0];
    const float* rois = (const float*)d_in[1];
    float* out = (float*)d_out;

    transpose_kernel<<<8 * NCG * H_, 256>>>(x);
    roi_fp16<<<R_ * NCG, 256>>>(rois, out);
}

// round 10
// speedup vs baseline: 1.0345x; 1.0345x over previous
#include <cuda_runtime.h>
#include <cuda_fp16.h>
#include <cstdint>

// ROI Align, P=7, S=2, SCALE=0.125
// x: (8, 256, 100, 100) fp32   rois: (512, 5) fp32   out: (512, 256, 7, 7) fp32
//
// 1) transpose_kernel: NCHW fp32 -> NHWC-256 fp16 slab (41MB), permuted so
//    lane l of the main kernel owns logical channels {l, l+32, ..., l+224}.
// 2) roi_fp16: block = roi. Warp = one bin x 256 channels; each tap is one
//    LDG.128 (512B/warp). Horizontal interp in fp16 (HFMA2), vertical in fp32.

#define C_    256
#define H_    100
#define W_    100
#define HW_   10000
#define R_    512
#define PIXU4 32                    // uint4 per pixel (256ch fp16 = 512B)
#define ROWU4 (W_ * PIXU4)          // 3200
#define TSTR  129                   // transpose smem stride (words)

// fp16 slab: 8 * 10000 * 128 uints = 40.96 MB
__device__ unsigned int g_xt[8 * HW_ * 128];

__device__ __forceinline__ void axis_terms(float c, int L,
                                           int& lo, int& hi,
                                           float& wlo, float& whi) {
    bool valid = (c > -1.0f) && (c < (float)L);
    float cc = fminf(fmaxf(c, 0.0f), (float)(L - 1));
    int l = (int)floorf(cc);
    if (l > L - 1) l = L - 1;
    int h = min(l + 1, L - 1);
    float frac = cc - (float)l;
    lo = l; hi = h;
    wlo = valid ? (1.0f - frac) : 0.0f;
    whi = valid ? frac : 0.0f;
}

// block = (b, y): 256 channels x 100 px -> fp16 channel-major (permuted).
// slab uint u = 4l + k' packs logical channels (64k'+l, 64k'+l+32).
__global__ void __launch_bounds__(256)
transpose_kernel(const float* __restrict__ x) {
    extern __shared__ unsigned int s2[];   // [xx][u] half2, stride 129

    const int y   = blockIdx.x % H_;
    const int b   = blockIdx.x / H_;
    const int tid = threadIdx.x;

    const float* srcb = x + (size_t)b * (C_ * HW_) + y * W_;

    // phase 1: u in [0,128) x x2 in [0,50); float2 loads, 2-way-max STS
    for (int i = tid; i < 128 * 50; i += 256) {
        int u  = i / 50;
        int x2 = i - u * 50;
        int cA = ((u & 3) << 6) + (u >> 2);
        float2 a = __ldg((const float2*)(srcb + (size_t)cA * HW_) + x2);
        float2 c = __ldg((const float2*)(srcb + (size_t)(cA + 32) * HW_) + x2);
        __half2 h0 = __floats2half2_rn(a.x, c.x);
        __half2 h1 = __floats2half2_rn(a.y, c.y);
        s2[(2 * x2) * TSTR + u]     = *(unsigned int*)&h0;
        s2[(2 * x2 + 1) * TSTR + u] = *(unsigned int*)&h1;
    }
    __syncthreads();

    // phase 2: 100 px x 32 uint4; LDS.128 + STG.128, 51.2KB contiguous run
    uint4* dst = (uint4*)g_xt + ((size_t)b * HW_ + (size_t)y * W_) * PIXU4;
    for (int j = tid; j < W_ * PIXU4; j += 256) {
        int px = j >> 5;
        int q  = j & 31;
        const unsigned int* sp = s2 + px * TSTR + 4 * q;
        dst[px * PIXU4 + q] = make_uint4(sp[0], sp[1], sp[2], sp[3]);
    }
}

// block = roi, 256 threads / 8 warps over 49 bins; warp covers all 256 ch.
__global__ void __launch_bounds__(256)
roi_fp16(const float* __restrict__ rois, float* __restrict__ out) {
    __shared__ int4 sg[28];           // y: {lo*3200, hi*3200, wy0*.25f32, wy1*.25f32}
                                      // x: {xb*32, h2splat(wx0), h2splat(wx1), 0}
    extern __shared__ __align__(16) float sout[];   // 256*49 floats = 50176B

    const int r   = blockIdx.x;
    const int tid = threadIdx.x;

    const float* roi = rois + (size_t)r * 5;
    float r0 = __ldg(roi + 0);
    float r1 = __ldg(roi + 1);
    float r2 = __ldg(roi + 2);
    float r3 = __ldg(roi + 3);
    float r4 = __ldg(roi + 4);

    const int b = (int)r0;
    const float sx = r1 * 0.125f - 0.5f;
    const float sy = r2 * 0.125f - 0.5f;
    const float bw = (r3 * 0.125f - 0.5f - sx) * (1.0f / 7.0f);
    const float bh = (r4 * 0.125f - 0.5f - sy) * (1.0f / 7.0f);

    if (tid < 14) {
        int s = tid;
        float pos = fmaf((float)(s >> 1) + ((s & 1) ? 0.75f : 0.25f), bh, sy);
        int lo, hi; float w0, w1;
        axis_terms(pos, H_, lo, hi, w0, w1);
        sg[s] = make_int4(lo * ROWU4, hi * ROWU4,
                          __float_as_int(w0 * 0.25f), __float_as_int(w1 * 0.25f));
    } else if (tid >= 16 && tid < 30) {
        int s2i = tid - 16;
        float pos = fmaf((float)(s2i >> 1) + ((s2i & 1) ? 0.75f : 0.25f), bw, sx);
        int lo, hi; float w0, w1;
        axis_terms(pos, W_, lo, hi, w0, w1);
        int xb; float v0, v1;
        if (lo == W_ - 1) { xb = W_ - 2; v0 = 0.0f; v1 = w0 + w1; }
        else              { xb = lo;     v0 = w0;   v1 = w1; }
        __half2 s0 = __float2half2_rn(v0);
        __half2 s1 = __float2half2_rn(v1);
        sg[14 + s2i] = make_int4(xb * PIXU4,
                                 *(int*)&s0, *(int*)&s1, 0);
    }
    __syncthreads();

    const int warp = tid >> 5;
    const int lane = tid & 31;
    const uint4* base = (const uint4*)g_xt + (size_t)b * (HW_ * PIXU4) + lane;

    for (int bin = warp; bin < 49; bin += 8) {
        int ph = (bin * 147) >> 10;       // bin / 7 for bin < 49
        int pw = bin - ph * 7;

        int4 gy0 = sg[2 * ph];
        int4 gy1 = sg[2 * ph + 1];
        int4 gx0 = sg[14 + 2 * pw];
        int4 gx1 = sg[14 + 2 * pw + 1];

        const int xoff = gx0.x;
        const int dx   = gx1.x - gx0.x;
        const __half2 w0s = *(__half2*)&gx0.y;
        const __half2 w1s = *(__half2*)&gx0.z;
        const __half2 w2s = *(__half2*)&gx1.y;
        const __half2 w3s = *(__half2*)&gx1.z;

        const int   roff[4] = {gy0.x, gy0.y, gy1.x, gy1.y};
        const float wy[4]   = {__int_as_float(gy0.z), __int_as_float(gy0.w),
                               __int_as_float(gy1.z), __int_as_float(gy1.w)};

        float acc[8] = {0.f, 0.f, 0.f, 0.f, 0.f, 0.f, 0.f, 0.f};

#pragma unroll
        for (int rr = 0; rr < 4; rr++) {
            const uint4* pr = base + roff[rr] + xoff;
            uint4 t0 = __ldg(pr);
            uint4 t1 = __ldg(pr + PIXU4);
            uint4 t2 = __ldg(pr + dx);
            uint4 t3 = __ldg(pr + dx + PIXU4);
            const __half2* a0 = (const __half2*)&t0;
            const __half2* a1 = (const __half2*)&t1;
            const __half2* a2 = (const __half2*)&t2;
            const __half2* a3 = (const __half2*)&t3;
            float wyr = wy[rr];
#pragma unroll
            for (int m = 0; m < 4; m++) {
                __half2 hv = __hmul2(w0s, a0[m]);
                hv = __hfma2(w1s, a1[m], hv);
                hv = __hfma2(w2s, a2[m], hv);
                hv = __hfma2(w3s, a3[m], hv);
                float2 f2 = __half22float2(hv);
                acc[2 * m]     = fmaf(wyr, f2.x, acc[2 * m]);
                acc[2 * m + 1] = fmaf(wyr, f2.y, acc[2 * m + 1]);
            }
        }

        // acc[j] is channel 32j + lane -> stride-49 STS, conflict-free
        float* so = sout + lane * 49 + bin;
#pragma unroll
        for (int j = 0; j < 8; j++)
            so[j * (32 * 49)] = acc[j];
    }
    __syncthreads();

    float4* op = (float4*)(out + (size_t)r * (C_ * 49));
    const float4* sp = (const float4*)sout;
    for (int i = tid; i < C_ * 49 / 4; i += 256)
        op[i] = sp[i];
}

extern "C" void kernel_launch(void* const* d_in, const int* in_sizes, int n_in,
                              void* d_out, int out_size) {
    const float* x    = (const float*)d_in[0];
    const float* rois = (const float*)d_in[1];
    float* out = (float*)d_out;

    const int tsmem = W_ * TSTR * 4;          // 51600 B
    const int msmem = C_ * 49 * 4;            // 50176 B
    cudaFuncSetAttribute(transpose_kernel,
                         cudaFuncAttributeMaxDynamicSharedMemorySize, tsmem);
    cudaFuncSetAttribute(roi_fp16,
                         cudaFuncAttributeMaxDynamicSharedMemorySize, msmem);

    transpose_kernel<<<8 * H_, 256, tsmem>>>(x);
    roi_fp16<<<R_, 256, msmem>>>(rois, out);
}

// round 12
// speedup vs baseline: 1.0696x; 1.0340x over previous
#include <cuda_runtime.h>
#include <cuda_fp16.h>
#include <cstdint>

// ROI Align, P=7, S=2, SCALE=0.125
// x: (8, 256, 100, 100) fp32   rois: (512, 5) fp32   out: (512, 256, 7, 7) fp32
//
// 1) transpose_kernel: NCHW fp32 -> NHWC-256 fp16 slab (41MB).
//    u-major smem (pad 102): float4 loads, STS.64 conflict-free, phase-2
//    LDS stride-102 (2-way max) + STG.128. Slab uint4 at (pix, q) packs
//    u = {q, q+32, q+64, q+96}; uint u packs channels (64*(u>>5)+(u&31), +32).
//    => main-kernel lane l, half2 m: channels (64m+l, 64m+l+32) = {32j+l}.
// 2) roi_fp16: block = roi. Warp = one bin x 256 channels; each tap is one
//    LDG.128 (512B/warp). Horizontal interp fp16 (HFMA2), vertical fp32.

#define C_    256
#define H_    100
#define W_    100
#define HW_   10000
#define R_    512
#define PIXU4 32                    // uint4 per pixel (256ch fp16 = 512B)
#define ROWU4 (W_ * PIXU4)          // 3200
#define TPAD  102                   // transpose smem row pad (words)

// fp16 slab: 8 * 10000 * 128 uints = 40.96 MB
__device__ unsigned int g_xt[8 * HW_ * 128];

__device__ __forceinline__ void axis_terms(float c, int L,
                                           int& lo, int& hi,
                                           float& wlo, float& whi) {
    bool valid = (c > -1.0f) && (c < (float)L);
    float cc = fminf(fmaxf(c, 0.0f), (float)(L - 1));
    int l = (int)floorf(cc);
    if (l > L - 1) l = L - 1;
    int h = min(l + 1, L - 1);
    float frac = cc - (float)l;
    lo = l; hi = h;
    wlo = valid ? (1.0f - frac) : 0.0f;
    whi = valid ? frac : 0.0f;
}

// block = (b, y): 256 channels x 100 px -> fp16 channel-major (permuted).
__global__ void __launch_bounds__(256)
transpose_kernel(const float* __restrict__ x) {
    extern __shared__ unsigned int s2[];   // [u][px], pad 102: 52224 B

    const int y   = blockIdx.x % H_;
    const int b   = blockIdx.x / H_;
    const int tid = threadIdx.x;

    const float* srcb = x + (size_t)b * (C_ * HW_) + y * W_;

    // phase 1: u in [0,128) x x4 in [0,25). 2x LDG.128, 4x F2FP, 2x STS.64.
    for (int i = tid; i < 128 * 25; i += 256) {
        int u  = i / 25;
        int x4 = i - u * 25;
        int cA = ((u >> 5) << 6) | (u & 31);
        float4 a = __ldg((const float4*)(srcb + (size_t)cA * HW_) + x4);
        float4 c = __ldg((const float4*)(srcb + (size_t)(cA + 32) * HW_) + x4);
        __half2 h0 = __floats2half2_rn(a.x, c.x);
        __half2 h1 = __floats2half2_rn(a.y, c.y);
        __half2 h2 = __floats2half2_rn(a.z, c.z);
        __half2 h3 = __floats2half2_rn(a.w, c.w);
        unsigned int* sp = s2 + u * TPAD + 4 * x4;
        *(uint2*)(sp)     = make_uint2(*(unsigned int*)&h0, *(unsigned int*)&h1);
        *(uint2*)(sp + 2) = make_uint2(*(unsigned int*)&h2, *(unsigned int*)&h3);
    }
    __syncthreads();

    // phase 2: lane q gathers u = q+32k (stride-102 LDS, 2-way max), STG.128.
    uint4* dst = (uint4*)g_xt + ((size_t)b * HW_ + (size_t)y * W_) * PIXU4;
    for (int j = tid; j < W_ * PIXU4; j += 256) {
        int px = j >> 5;
        int q  = j & 31;
        const unsigned int* sp = s2 + q * TPAD + px;
        dst[px * PIXU4 + q] = make_uint4(sp[0],
                                         sp[32 * TPAD],
                                         sp[64 * TPAD],
                                         sp[96 * TPAD]);
    }
}

// block = roi, 256 threads / 8 warps over 49 bins; warp covers all 256 ch.
__global__ void __launch_bounds__(256)
roi_fp16(const float* __restrict__ rois, float* __restrict__ out) {
    __shared__ int4 sg[28];           // y: {lo*3200, hi*3200, wy0*.25f32, wy1*.25f32}
                                      // x: {xb*32, h2splat(wx0), h2splat(wx1), 0}
    extern __shared__ __align__(16) float sout[];   // 256*49 floats = 50176B

    const int r   = blockIdx.x;
    const int tid = threadIdx.x;

    const float* roi = rois + (size_t)r * 5;
    float r0 = __ldg(roi + 0);
    float r1 = __ldg(roi + 1);
    float r2 = __ldg(roi + 2);
    float r3 = __ldg(roi + 3);
    float r4 = __ldg(roi + 4);

    const int b = (int)r0;
    const float sx = r1 * 0.125f - 0.5f;
    const float sy = r2 * 0.125f - 0.5f;
    const float bw = (r3 * 0.125f - 0.5f - sx) * (1.0f / 7.0f);
    const float bh = (r4 * 0.125f - 0.5f - sy) * (1.0f / 7.0f);

    if (tid < 14) {
        int s = tid;
        float pos = fmaf((float)(s >> 1) + ((s & 1) ? 0.75f : 0.25f), bh, sy);
        int lo, hi; float w0, w1;
        axis_terms(pos, H_, lo, hi, w0, w1);
        sg[s] = make_int4(lo * ROWU4, hi * ROWU4,
                          __float_as_int(w0 * 0.25f), __float_as_int(w1 * 0.25f));
    } else if (tid >= 16 && tid < 30) {
        int s2i = tid - 16;
        float pos = fmaf((float)(s2i >> 1) + ((s2i & 1) ? 0.75f : 0.25f), bw, sx);
        int lo, hi; float w0, w1;
        axis_terms(pos, W_, lo, hi, w0, w1);
        int xb; float v0, v1;
        if (lo == W_ - 1) { xb = W_ - 2; v0 = 0.0f; v1 = w0 + w1; }
        else              { xb = lo;     v0 = w0;   v1 = w1; }
        __half2 s0 = __float2half2_rn(v0);
        __half2 s1 = __float2half2_rn(v1);
        sg[14 + s2i] = make_int4(xb * PIXU4,
                                 *(int*)&s0, *(int*)&s1, 0);
    }
    __syncthreads();

    const int warp = tid >> 5;
    const int lane = tid & 31;
    const uint4* base = (const uint4*)g_xt + (size_t)b * (HW_ * PIXU4) + lane;

    for (int bin = warp; bin < 49; bin += 8) {
        int ph = (bin * 147) >> 10;       // bin / 7 for bin < 49
        int pw = bin - ph * 7;

        int4 gy0 = sg[2 * ph];
        int4 gy1 = sg[2 * ph + 1];
        int4 gx0 = sg[14 + 2 * pw];
        int4 gx1 = sg[14 + 2 * pw + 1];

        const int xoff = gx0.x;
        const int dx   = gx1.x - gx0.x;
        const __half2 w0s = *(__half2*)&gx0.y;
        const __half2 w1s = *(__half2*)&gx0.z;
        const __half2 w2s = *(__half2*)&gx1.y;
        const __half2 w3s = *(__half2*)&gx1.z;

        const int   roff[4] = {gy0.x, gy0.y, gy1.x, gy1.y};
        const float wy[4]   = {__int_as_float(gy0.z), __int_as_float(gy0.w),
                               __int_as_float(gy1.z), __int_as_float(gy1.w)};

        float acc[8] = {0.f, 0.f, 0.f, 0.f, 0.f, 0.f, 0.f, 0.f};

#pragma unroll
        for (int rr = 0; rr < 4; rr++) {
            const uint4* pr = base + roff[rr] + xoff;
            uint4 t0 = __ldg(pr);
            uint4 t1 = __ldg(pr + PIXU4);
            uint4 t2 = __ldg(pr + dx);
            uint4 t3 = __ldg(pr + dx + PIXU4);
            const __half2* a0 = (const __half2*)&t0;
            const __half2* a1 = (const __half2*)&t1;
            const __half2* a2 = (const __half2*)&t2;
            const __half2* a3 = (const __half2*)&t3;
            float wyr = wy[rr];
#pragma unroll
            for (int m = 0; m < 4; m++) {
                __half2 hv = __hmul2(w0s, a0[m]);
                hv = __hfma2(w1s, a1[m], hv);
                hv = __hfma2(w2s, a2[m], hv);
                hv = __hfma2(w3s, a3[m], hv);
                float2 f2 = __half22float2(hv);
                acc[2 * m]     = fmaf(wyr, f2.x, acc[2 * m]);
                acc[2 * m + 1] = fmaf(wyr, f2.y, acc[2 * m + 1]);
            }
        }

        // acc[j] is channel 32j + lane -> stride-49 STS, conflict-free
        float* so = sout + lane * 49 + bin;
#pragma unroll
        for (int j = 0; j < 8; j++)
            so[j * (32 * 49)] = acc[j];
    }
    __syncthreads();

    float4* op = (float4*)(out + (size_t)r * (C_ * 49));
    const float4* sp = (const float4*)sout;
    for (int i = tid; i < C_ * 49 / 4; i += 256)
        op[i] = sp[i];
}

extern "C" void kernel_launch(void* const* d_in, const int* in_sizes, int n_in,
                              void* d_out, int out_size) {
    const float* x    = (const float*)d_in[0];
    const float* rois = (const float*)d_in[1];
    float* out = (float*)d_out;

    const int tsmem = 128 * TPAD * 4;         // 52224 B
    const int msmem = C_ * 49 * 4;            // 50176 B
    cudaFuncSetAttribute(transpose_kernel,
                         cudaFuncAttributeMaxDynamicSharedMemorySize, tsmem);
    cudaFuncSetAttribute(roi_fp16,
                         cudaFuncAttributeMaxDynamicSharedMemorySize, msmem);

    transpose_kernel<<<8 * H_, 256, tsmem>>>(x);
    roi_fp16<<<R_, 256, msmem>>>(rois, out);
}